// round 2
// baseline (speedup 1.0000x reference)
#include <cuda_runtime.h>
#include <cstdint>

#define N_NODES 100000
#define F_IN    512
#define MAX_E   3200000

// -------- device scratch --------
__device__ int   g_is64;
__device__ int   g_src[MAX_E];
__device__ int   g_dst[MAX_E];
__device__ int   g_rank[MAX_E];
__device__ int   g_csr[MAX_E];        // src ids sorted by dst
__device__ int   g_deg[N_NODES];      // in-edge count (no self-loop)
__device__ int   g_ptr[N_NODES + 1];  // CSR offsets
__device__ float g_dinv[N_NODES];
__device__ float g_h1[N_NODES * 16];  // x @ W1
__device__ float g_h2[N_NODES * 8];   // relu(agg1+b1) @ W2, padded to 8

// -------- dtype detection: int64 edge_index has zero high words --------
__global__ void k_detect(const unsigned int* ei) {
    __shared__ int nz;
    if (threadIdx.x == 0) nz = 0;
    __syncthreads();
    for (int i = threadIdx.x; i < 2048; i += blockDim.x)
        if (ei[2 * i + 1] != 0u) nz = 1;
    __syncthreads();
    if (threadIdx.x == 0) g_is64 = (nz == 0) ? 1 : 0;
}

__global__ void k_initdeg() {
    int i = blockIdx.x * blockDim.x + threadIdx.x;
    if (i < N_NODES) g_deg[i] = 0;
}

// convert edges to int32 + degree histogram; atomic return = stable rank
__global__ void k_convert(const void* ei, int E) {
    int e = blockIdx.x * blockDim.x + threadIdx.x;
    if (e >= E) return;
    int s, d;
    if (g_is64) {
        const long long* p = (const long long*)ei;
        s = (int)p[e];
        d = (int)p[E + e];
    } else {
        const int* p = (const int*)ei;
        s = p[e];
        d = p[E + e];
    }
    g_src[e]  = s;
    g_dst[e]  = d;
    g_rank[e] = atomicAdd(&g_deg[d], 1);
}

// single-block scan: CSR offsets + dinv (deg incl. self-loop)
__global__ void __launch_bounds__(1024) k_scan() {
    __shared__ int part[1024];
    const int C = (N_NODES + 1023) / 1024;  // 98
    int t = threadIdx.x;
    int base = t * C;
    int sum = 0;
#pragma unroll 7
    for (int i = 0; i < C; i++) {
        int n = base + i;
        if (n < N_NODES) sum += g_deg[n];
    }
    part[t] = sum;
    __syncthreads();
    for (int off = 1; off < 1024; off <<= 1) {
        int v = 0;
        if (t >= off) v = part[t - off];
        __syncthreads();
        if (t >= off) part[t] += v;
        __syncthreads();
    }
    int run = (t > 0) ? part[t - 1] : 0;
    for (int i = 0; i < C; i++) {
        int n = base + i;
        if (n < N_NODES) {
            int dg = g_deg[n];
            g_ptr[n]  = run;
            g_dinv[n] = rsqrtf((float)(dg + 1));
            run += dg;
        }
    }
    if (t == 0) g_ptr[N_NODES] = part[1023];
}

// atomic-free scatter into CSR
__global__ void k_scatter(int E) {
    int e = blockIdx.x * blockDim.x + threadIdx.x;
    if (e >= E) return;
    int d = g_dst[e];
    g_csr[g_ptr[d] + g_rank[e]] = g_src[e];
}

// -------- GEMM: h1 = x @ W1 (FFMA2 inner product) --------
#define KC 32
#define XS_STRIDE 36

__global__ void __launch_bounds__(256) k_gemm1(const float* __restrict__ x,
                                               const float* __restrict__ W1) {
    __shared__ float xs[256 * XS_STRIDE];
    __shared__ float wc[KC * 16];
    int t = threadIdx.x;
    int rbase = blockIdx.x * 256;

    unsigned long long acc[8];
#pragma unroll
    for (int j = 0; j < 8; j++) acc[j] = 0ull;

    for (int kb = 0; kb < F_IN; kb += KC) {
        __syncthreads();
#pragma unroll
        for (int i = 0; i < 8; i++) {
            int flat = t + 256 * i;
            int row  = flat >> 3;
            int k4   = flat & 7;
            float4 v = make_float4(0.f, 0.f, 0.f, 0.f);
            int gr = rbase + row;
            if (gr < N_NODES)
                v = *(const float4*)(x + (size_t)gr * F_IN + kb + k4 * 4);
            *(float4*)(xs + row * XS_STRIDE + k4 * 4) = v;
        }
        if (t < 128)
            *(float4*)(wc + t * 4) = *(const float4*)(W1 + kb * 16 + t * 4);
        __syncthreads();

#pragma unroll
        for (int k4 = 0; k4 < 8; k4++) {
            float4 xv = *(float4*)(xs + t * XS_STRIDE + k4 * 4);
            float xk[4] = {xv.x, xv.y, xv.z, xv.w};
#pragma unroll
            for (int c = 0; c < 4; c++) {
                int k = k4 * 4 + c;
                unsigned long long xx;
                asm("mov.b64 %0, {%1,%1};" : "=l"(xx) : "f"(xk[c]));
                const unsigned long long* wr =
                    (const unsigned long long*)(wc + k * 16);
#pragma unroll
                for (int j = 0; j < 8; j++)
                    asm("fma.rn.f32x2 %0, %1, %2, %0;"
                        : "+l"(acc[j]) : "l"(xx), "l"(wr[j]));
            }
        }
    }

    int r = rbase + t;
    if (r < N_NODES) {
        float4* hp = (float4*)(g_h1 + (size_t)r * 16);
#pragma unroll
        for (int q = 0; q < 4; q++) {
            float lo0, hi0, lo1, hi1;
            asm("mov.b64 {%0,%1}, %2;" : "=f"(lo0), "=f"(hi0) : "l"(acc[2 * q]));
            asm("mov.b64 {%0,%1}, %2;" : "=f"(lo1), "=f"(hi1) : "l"(acc[2 * q + 1]));
            hp[q] = make_float4(lo0, hi0, lo1, hi1);
        }
    }
}

// -------- layer 1 aggregate (CSR gather) fused with layer 2 transform --------
__global__ void __launch_bounds__(256) k_agg1x(const float* __restrict__ b1,
                                               const float* __restrict__ W2) {
    __shared__ float sW[128];  // [0:112) W2 row-major [16,7], [112:128) b1
    int t = threadIdx.x;
    if (t < 112) sW[t] = W2[t];
    else if (t < 128) sW[t] = b1[t - 112];
    __syncthreads();

    int n = blockIdx.x * blockDim.x + t;
    if (n >= N_NODES) return;

    float di  = g_dinv[n];
    float di2 = di * di;
    float acc[16];
    {
        const float4* hp = (const float4*)(g_h1 + (size_t)n * 16);
#pragma unroll
        for (int q = 0; q < 4; q++) {
            float4 v = hp[q];
            acc[4 * q + 0] = v.x * di2;
            acc[4 * q + 1] = v.y * di2;
            acc[4 * q + 2] = v.z * di2;
            acc[4 * q + 3] = v.w * di2;
        }
    }
    int beg = g_ptr[n], end = g_ptr[n + 1];
    int i = beg;
    for (; i + 2 <= end; i += 2) {
        int s0 = g_csr[i], s1 = g_csr[i + 1];
        float n0 = g_dinv[s0] * di, n1 = g_dinv[s1] * di;
        const float4* q0 = (const float4*)(g_h1 + (size_t)s0 * 16);
        const float4* q1 = (const float4*)(g_h1 + (size_t)s1 * 16);
#pragma unroll
        for (int q = 0; q < 4; q++) {
            float4 a = q0[q], b = q1[q];
            acc[4 * q + 0] += a.x * n0 + b.x * n1;
            acc[4 * q + 1] += a.y * n0 + b.y * n1;
            acc[4 * q + 2] += a.z * n0 + b.z * n1;
            acc[4 * q + 3] += a.w * n0 + b.w * n1;
        }
    }
    if (i < end) {
        int s0 = g_csr[i];
        float n0 = g_dinv[s0] * di;
        const float4* q0 = (const float4*)(g_h1 + (size_t)s0 * 16);
#pragma unroll
        for (int q = 0; q < 4; q++) {
            float4 a = q0[q];
            acc[4 * q + 0] += a.x * n0;
            acc[4 * q + 1] += a.y * n0;
            acc[4 * q + 2] += a.z * n0;
            acc[4 * q + 3] += a.w * n0;
        }
    }
    // relu(acc + b1) @ W2 -> h2 (padded to 8)
    float v[16];
#pragma unroll
    for (int k = 0; k < 16; k++) v[k] = fmaxf(acc[k] + sW[112 + k], 0.f);
    float h[7];
#pragma unroll
    for (int j = 0; j < 7; j++) {
        float s = 0.f;
#pragma unroll
        for (int k = 0; k < 16; k++) s += v[k] * sW[k * 7 + j];
        h[j] = s;
    }
    float4* hp = (float4*)(g_h2 + (size_t)n * 8);
    hp[0] = make_float4(h[0], h[1], h[2], h[3]);
    hp[1] = make_float4(h[4], h[5], h[6], 0.f);
}

// -------- layer 2 aggregate (CSR gather), writes d_out directly --------
__global__ void __launch_bounds__(256) k_agg2(const float* __restrict__ b2,
                                              float* __restrict__ out) {
    int n = blockIdx.x * blockDim.x + threadIdx.x;
    if (n >= N_NODES) return;
    float di  = g_dinv[n];
    float di2 = di * di;
    float acc[7];
    {
        const float4* hp = (const float4*)(g_h2 + (size_t)n * 8);
        float4 a = hp[0], b = hp[1];
        acc[0] = a.x * di2 + __ldg(b2 + 0);
        acc[1] = a.y * di2 + __ldg(b2 + 1);
        acc[2] = a.z * di2 + __ldg(b2 + 2);
        acc[3] = a.w * di2 + __ldg(b2 + 3);
        acc[4] = b.x * di2 + __ldg(b2 + 4);
        acc[5] = b.y * di2 + __ldg(b2 + 5);
        acc[6] = b.z * di2 + __ldg(b2 + 6);
    }
    int beg = g_ptr[n], end = g_ptr[n + 1];
    int i = beg;
    for (; i + 2 <= end; i += 2) {
        int s0 = g_csr[i], s1 = g_csr[i + 1];
        float n0 = g_dinv[s0] * di, n1 = g_dinv[s1] * di;
        const float4* p0 = (const float4*)(g_h2 + (size_t)s0 * 8);
        const float4* p1 = (const float4*)(g_h2 + (size_t)s1 * 8);
        float4 a0 = p0[0], a1 = p0[1], c0 = p1[0], c1 = p1[1];
        acc[0] += a0.x * n0 + c0.x * n1;
        acc[1] += a0.y * n0 + c0.y * n1;
        acc[2] += a0.z * n0 + c0.z * n1;
        acc[3] += a0.w * n0 + c0.w * n1;
        acc[4] += a1.x * n0 + c1.x * n1;
        acc[5] += a1.y * n0 + c1.y * n1;
        acc[6] += a1.z * n0 + c1.z * n1;
    }
    if (i < end) {
        int s0 = g_csr[i];
        float n0 = g_dinv[s0] * di;
        const float4* p0 = (const float4*)(g_h2 + (size_t)s0 * 8);
        float4 a0 = p0[0], a1 = p0[1];
        acc[0] += a0.x * n0;
        acc[1] += a0.y * n0;
        acc[2] += a0.z * n0;
        acc[3] += a0.w * n0;
        acc[4] += a1.x * n0;
        acc[5] += a1.y * n0;
        acc[6] += a1.z * n0;
    }
    float* op = out + (size_t)n * 7;
#pragma unroll
    for (int j = 0; j < 7; j++) op[j] = acc[j];
}

extern "C" void kernel_launch(void* const* d_in, const int* in_sizes, int n_in,
                              void* d_out, int out_size) {
    const float* x  = (const float*)d_in[0];
    const void*  ei = d_in[1];
    const float* W1 = (const float*)d_in[2];
    const float* b1 = (const float*)d_in[3];
    const float* W2 = (const float*)d_in[4];
    const float* b2 = (const float*)d_in[5];
    int E = in_sizes[1] / 2;

    k_detect<<<1, 256>>>((const unsigned int*)ei);
    k_initdeg<<<(N_NODES + 255) / 256, 256>>>();
    k_convert<<<(E + 255) / 256, 256>>>(ei, E);
    k_scan<<<1, 1024>>>();
    k_scatter<<<(E + 255) / 256, 256>>>(E);
    k_gemm1<<<(N_NODES + 255) / 256, 256>>>(x, W1);
    k_agg1x<<<(N_NODES + 255) / 256, 256>>>(b1, W2);
    k_agg2<<<(N_NODES + 255) / 256, 256>>>(b2, (float*)d_out);
}

// round 3
// speedup vs baseline: 1.5725x; 1.5725x over previous
#include <cuda_runtime.h>
#include <cstdint>

#define N_NODES 100000
#define F_IN    512
#define MAX_E   3200000
#define SCAN_B  1024
#define SCAN_G  ((N_NODES + SCAN_B - 1) / SCAN_B)   // 98

// -------- device scratch --------
__device__ int   g_is64;
__device__ int   g_src[MAX_E];
__device__ int   g_dst[MAX_E];
__device__ int   g_rank[MAX_E];
__device__ int   g_csr[MAX_E];        // src ids sorted by dst
__device__ int   g_deg[N_NODES];      // in-edge count (no self-loop)
__device__ int   g_ptr[N_NODES + 1];  // CSR offsets
__device__ int   g_bsum[SCAN_G];
__device__ int   g_boff[SCAN_G];
__device__ float g_dinv[N_NODES];
__device__ float g_h1[N_NODES * 16];  // x @ W1
__device__ float g_h2[N_NODES * 8];   // relu(agg1+b1) @ W2, padded to 8

// -------- dtype detection: int64 edge_index has zero high words --------
__global__ void k_detect(const unsigned int* ei) {
    __shared__ int nz;
    if (threadIdx.x == 0) nz = 0;
    __syncthreads();
    for (int i = threadIdx.x; i < 2048; i += blockDim.x)
        if (ei[2 * i + 1] != 0u) nz = 1;
    __syncthreads();
    if (threadIdx.x == 0) g_is64 = (nz == 0) ? 1 : 0;
}

__global__ void k_initdeg() {
    int i = blockIdx.x * blockDim.x + threadIdx.x;
    if (i < N_NODES) g_deg[i] = 0;
}

// convert edges to int32 + degree histogram; atomic return = stable rank
__global__ void k_convert(const void* ei, int E) {
    int e = blockIdx.x * blockDim.x + threadIdx.x;
    if (e >= E) return;
    int s, d;
    if (g_is64) {
        const long long* p = (const long long*)ei;
        s = (int)p[e];
        d = (int)p[E + e];
    } else {
        const int* p = (const int*)ei;
        s = p[e];
        d = p[E + e];
    }
    g_src[e]  = s;
    g_dst[e]  = d;
    g_rank[e] = atomicAdd(&g_deg[d], 1);
}

// -------- 3-phase scan --------
// phase 1: block-local exclusive scan + block sums + dinv
__global__ void __launch_bounds__(SCAN_B) k_scan1() {
    __shared__ int s[SCAN_B];
    int t = threadIdx.x;
    int n = blockIdx.x * SCAN_B + t;
    int dg = (n < N_NODES) ? g_deg[n] : 0;
    s[t] = dg;
    __syncthreads();
#pragma unroll
    for (int off = 1; off < SCAN_B; off <<= 1) {
        int v = (t >= off) ? s[t - off] : 0;
        __syncthreads();
        s[t] += v;
        __syncthreads();
    }
    if (n < N_NODES) {
        g_ptr[n]  = s[t] - dg;                 // local exclusive prefix
        g_dinv[n] = rsqrtf((float)(dg + 1));   // self-loop incl.
    }
    if (t == SCAN_B - 1) g_bsum[blockIdx.x] = s[t];
}

// phase 2: scan the 98 block sums (single warp)
__global__ void k_scan2() {
    if (threadIdx.x == 0) {
        int run = 0;
        for (int b = 0; b < SCAN_G; b++) {
            g_boff[b] = run;
            run += g_bsum[b];
        }
        g_ptr[N_NODES] = run;
    }
}

// phase 3: apply block offsets
__global__ void __launch_bounds__(SCAN_B) k_scan3() {
    int n = blockIdx.x * SCAN_B + threadIdx.x;
    if (n < N_NODES) g_ptr[n] += g_boff[blockIdx.x];
}

// atomic-free scatter into CSR
__global__ void k_scatter(int E) {
    int e = blockIdx.x * blockDim.x + threadIdx.x;
    if (e >= E) return;
    int d = g_dst[e];
    g_csr[g_ptr[d] + g_rank[e]] = g_src[e];
}

// -------- GEMM: h1 = x @ W1 (FFMA2 inner product) --------
#define KC 32
#define XS_STRIDE 36

__global__ void __launch_bounds__(256) k_gemm1(const float* __restrict__ x,
                                               const float* __restrict__ W1) {
    __shared__ float xs[256 * XS_STRIDE];
    __shared__ float wc[KC * 16];
    int t = threadIdx.x;
    int rbase = blockIdx.x * 256;

    unsigned long long acc[8];
#pragma unroll
    for (int j = 0; j < 8; j++) acc[j] = 0ull;

    for (int kb = 0; kb < F_IN; kb += KC) {
        __syncthreads();
#pragma unroll
        for (int i = 0; i < 8; i++) {
            int flat = t + 256 * i;
            int row  = flat >> 3;
            int k4   = flat & 7;
            float4 v = make_float4(0.f, 0.f, 0.f, 0.f);
            int gr = rbase + row;
            if (gr < N_NODES)
                v = *(const float4*)(x + (size_t)gr * F_IN + kb + k4 * 4);
            *(float4*)(xs + row * XS_STRIDE + k4 * 4) = v;
        }
        if (t < 128)
            *(float4*)(wc + t * 4) = *(const float4*)(W1 + kb * 16 + t * 4);
        __syncthreads();

#pragma unroll
        for (int k4 = 0; k4 < 8; k4++) {
            float4 xv = *(float4*)(xs + t * XS_STRIDE + k4 * 4);
            float xk[4] = {xv.x, xv.y, xv.z, xv.w};
#pragma unroll
            for (int c = 0; c < 4; c++) {
                int k = k4 * 4 + c;
                unsigned long long xx;
                asm("mov.b64 %0, {%1,%1};" : "=l"(xx) : "f"(xk[c]));
                const unsigned long long* wr =
                    (const unsigned long long*)(wc + k * 16);
#pragma unroll
                for (int j = 0; j < 8; j++)
                    asm("fma.rn.f32x2 %0, %1, %2, %0;"
                        : "+l"(acc[j]) : "l"(xx), "l"(wr[j]));
            }
        }
    }

    int r = rbase + t;
    if (r < N_NODES) {
        float4* hp = (float4*)(g_h1 + (size_t)r * 16);
#pragma unroll
        for (int q = 0; q < 4; q++) {
            float lo0, hi0, lo1, hi1;
            asm("mov.b64 {%0,%1}, %2;" : "=f"(lo0), "=f"(hi0) : "l"(acc[2 * q]));
            asm("mov.b64 {%0,%1}, %2;" : "=f"(lo1), "=f"(hi1) : "l"(acc[2 * q + 1]));
            hp[q] = make_float4(lo0, hi0, lo1, hi1);
        }
    }
}

// -------- layer 1 aggregate (CSR gather) fused with layer 2 transform --------
__global__ void __launch_bounds__(256) k_agg1x(const float* __restrict__ b1,
                                               const float* __restrict__ W2) {
    __shared__ float sW[128];  // [0:112) W2 row-major [16,7], [112:128) b1
    int t = threadIdx.x;
    if (t < 112) sW[t] = W2[t];
    else if (t < 128) sW[t] = b1[t - 112];
    __syncthreads();

    int n = blockIdx.x * blockDim.x + t;
    if (n >= N_NODES) return;

    float di  = g_dinv[n];
    float di2 = di * di;
    float acc[16];
    {
        const float4* hp = (const float4*)(g_h1 + (size_t)n * 16);
#pragma unroll
        for (int q = 0; q < 4; q++) {
            float4 v = hp[q];
            acc[4 * q + 0] = v.x * di2;
            acc[4 * q + 1] = v.y * di2;
            acc[4 * q + 2] = v.z * di2;
            acc[4 * q + 3] = v.w * di2;
        }
    }
    int beg = g_ptr[n], end = g_ptr[n + 1];
    int i = beg;
    for (; i + 2 <= end; i += 2) {
        int s0 = g_csr[i], s1 = g_csr[i + 1];
        float n0 = g_dinv[s0] * di, n1 = g_dinv[s1] * di;
        const float4* q0 = (const float4*)(g_h1 + (size_t)s0 * 16);
        const float4* q1 = (const float4*)(g_h1 + (size_t)s1 * 16);
#pragma unroll
        for (int q = 0; q < 4; q++) {
            float4 a = q0[q], b = q1[q];
            acc[4 * q + 0] += a.x * n0 + b.x * n1;
            acc[4 * q + 1] += a.y * n0 + b.y * n1;
            acc[4 * q + 2] += a.z * n0 + b.z * n1;
            acc[4 * q + 3] += a.w * n0 + b.w * n1;
        }
    }
    if (i < end) {
        int s0 = g_csr[i];
        float n0 = g_dinv[s0] * di;
        const float4* q0 = (const float4*)(g_h1 + (size_t)s0 * 16);
#pragma unroll
        for (int q = 0; q < 4; q++) {
            float4 a = q0[q];
            acc[4 * q + 0] += a.x * n0;
            acc[4 * q + 1] += a.y * n0;
            acc[4 * q + 2] += a.z * n0;
            acc[4 * q + 3] += a.w * n0;
        }
    }
    // relu(acc + b1) @ W2 -> h2 (padded to 8)
    float v[16];
#pragma unroll
    for (int k = 0; k < 16; k++) v[k] = fmaxf(acc[k] + sW[112 + k], 0.f);
    float h[7];
#pragma unroll
    for (int j = 0; j < 7; j++) {
        float s = 0.f;
#pragma unroll
        for (int k = 0; k < 16; k++) s += v[k] * sW[k * 7 + j];
        h[j] = s;
    }
    float4* hp = (float4*)(g_h2 + (size_t)n * 8);
    hp[0] = make_float4(h[0], h[1], h[2], h[3]);
    hp[1] = make_float4(h[4], h[5], h[6], 0.f);
}

// -------- layer 2 aggregate (CSR gather), writes d_out directly --------
__global__ void __launch_bounds__(256) k_agg2(const float* __restrict__ b2,
                                              float* __restrict__ out) {
    int n = blockIdx.x * blockDim.x + threadIdx.x;
    if (n >= N_NODES) return;
    float di  = g_dinv[n];
    float di2 = di * di;
    float acc[7];
    {
        const float4* hp = (const float4*)(g_h2 + (size_t)n * 8);
        float4 a = hp[0], b = hp[1];
        acc[0] = a.x * di2 + __ldg(b2 + 0);
        acc[1] = a.y * di2 + __ldg(b2 + 1);
        acc[2] = a.z * di2 + __ldg(b2 + 2);
        acc[3] = a.w * di2 + __ldg(b2 + 3);
        acc[4] = b.x * di2 + __ldg(b2 + 4);
        acc[5] = b.y * di2 + __ldg(b2 + 5);
        acc[6] = b.z * di2 + __ldg(b2 + 6);
    }
    int beg = g_ptr[n], end = g_ptr[n + 1];
    int i = beg;
    for (; i + 2 <= end; i += 2) {
        int s0 = g_csr[i], s1 = g_csr[i + 1];
        float n0 = g_dinv[s0] * di, n1 = g_dinv[s1] * di;
        const float4* p0 = (const float4*)(g_h2 + (size_t)s0 * 8);
        const float4* p1 = (const float4*)(g_h2 + (size_t)s1 * 8);
        float4 a0 = p0[0], a1 = p0[1], c0 = p1[0], c1 = p1[1];
        acc[0] += a0.x * n0 + c0.x * n1;
        acc[1] += a0.y * n0 + c0.y * n1;
        acc[2] += a0.z * n0 + c0.z * n1;
        acc[3] += a0.w * n0 + c0.w * n1;
        acc[4] += a1.x * n0 + c1.x * n1;
        acc[5] += a1.y * n0 + c1.y * n1;
        acc[6] += a1.z * n0 + c1.z * n1;
    }
    if (i < end) {
        int s0 = g_csr[i];
        float n0 = g_dinv[s0] * di;
        const float4* p0 = (const float4*)(g_h2 + (size_t)s0 * 8);
        float4 a0 = p0[0], a1 = p0[1];
        acc[0] += a0.x * n0;
        acc[1] += a0.y * n0;
        acc[2] += a0.z * n0;
        acc[3] += a0.w * n0;
        acc[4] += a1.x * n0;
        acc[5] += a1.y * n0;
        acc[6] += a1.z * n0;
    }
    float* op = out + (size_t)n * 7;
#pragma unroll
    for (int j = 0; j < 7; j++) op[j] = acc[j];
}

extern "C" void kernel_launch(void* const* d_in, const int* in_sizes, int n_in,
                              void* d_out, int out_size) {
    const float* x  = (const float*)d_in[0];
    const void*  ei = d_in[1];
    const float* W1 = (const float*)d_in[2];
    const float* b1 = (const float*)d_in[3];
    const float* W2 = (const float*)d_in[4];
    const float* b2 = (const float*)d_in[5];
    int E = in_sizes[1] / 2;

    k_detect<<<1, 256>>>((const unsigned int*)ei);
    k_initdeg<<<(N_NODES + 255) / 256, 256>>>();
    k_convert<<<(E + 255) / 256, 256>>>(ei, E);
    k_scan1<<<SCAN_G, SCAN_B>>>();
    k_scan2<<<1, 32>>>();
    k_scan3<<<SCAN_G, SCAN_B>>>();
    k_scatter<<<(E + 255) / 256, 256>>>(E);
    k_gemm1<<<(N_NODES + 255) / 256, 256>>>(x, W1);
    k_agg1x<<<(N_NODES + 255) / 256, 256>>>(b1, W2);
    k_agg2<<<(N_NODES + 255) / 256, 256>>>(b2, (float*)d_out);
}

// round 4
// speedup vs baseline: 1.6527x; 1.0510x over previous
#include <cuda_runtime.h>
#include <cstdint>

#define N_NODES 100000
#define F_IN    512
#define MAX_E   3200000
#define SCAN_B  1024
#define SCAN_G  ((N_NODES + SCAN_B - 1) / SCAN_B)   // 98

// -------- device scratch --------
__device__ int                g_is64;
__device__ unsigned long long g_pack[MAX_E];   // src | dst<<20 | rank<<40
__device__ int                g_csr[MAX_E];    // src ids sorted by dst
__device__ int                g_deg[N_NODES];
__device__ int                g_ptr[N_NODES + 1];  // block-local prefix; +boff = global
__device__ int                g_bsum[SCAN_G];
__device__ int                g_boff[SCAN_G];
__device__ float              g_dinv[N_NODES];
__device__ float              g_h1[N_NODES * 16];
__device__ float              g_h2[N_NODES * 8];

__device__ __forceinline__ int ptr_at(int n) {
    return (n == N_NODES) ? g_ptr[N_NODES] : g_ptr[n] + g_boff[n >> 10];
}

// -------- init: zero deg everywhere; block 0 also detects int64 vs int32 --------
__global__ void k_init(const unsigned int* ei) {
    int i = blockIdx.x * blockDim.x + threadIdx.x;
    if (i < N_NODES) g_deg[i] = 0;
    if (blockIdx.x == 0) {
        __shared__ int nz;
        if (threadIdx.x == 0) nz = 0;
        __syncthreads();
        for (int k = threadIdx.x; k < 2048; k += blockDim.x)
            if (ei[2 * k + 1] != 0u) nz = 1;
        __syncthreads();
        if (threadIdx.x == 0) g_is64 = (nz == 0) ? 1 : 0;
    }
}

// convert edges: pack (src,dst,rank) into u64; degree histogram
__global__ void k_convert(const void* ei, int E) {
    int e = blockIdx.x * blockDim.x + threadIdx.x;
    if (e >= E) return;
    unsigned int s, d;
    if (g_is64) {
        const long long* p = (const long long*)ei;
        s = (unsigned int)p[e];
        d = (unsigned int)p[E + e];
    } else {
        const unsigned int* p = (const unsigned int*)ei;
        s = p[e];
        d = p[E + e];
    }
    unsigned int r = (unsigned int)atomicAdd(&g_deg[d], 1);
    g_pack[e] = (unsigned long long)s | ((unsigned long long)d << 20)
              | ((unsigned long long)r << 40);
}

// scan phase 1: block-local exclusive prefix + block sums + dinv
__global__ void __launch_bounds__(SCAN_B) k_scan1() {
    __shared__ int s[SCAN_B];
    int t = threadIdx.x;
    int n = blockIdx.x * SCAN_B + t;
    int dg = (n < N_NODES) ? g_deg[n] : 0;
    s[t] = dg;
    __syncthreads();
#pragma unroll
    for (int off = 1; off < SCAN_B; off <<= 1) {
        int v = (t >= off) ? s[t - off] : 0;
        __syncthreads();
        s[t] += v;
        __syncthreads();
    }
    if (n < N_NODES) {
        g_ptr[n]  = s[t] - dg;
        g_dinv[n] = rsqrtf((float)(dg + 1));
    }
    if (t == SCAN_B - 1) g_bsum[blockIdx.x] = s[t];
}

// scan phase 2: parallel scan of 98 block sums
__global__ void __launch_bounds__(128) k_scan2() {
    __shared__ int s[128];
    int t = threadIdx.x;
    int v = (t < SCAN_G) ? g_bsum[t] : 0;
    s[t] = v;
    __syncthreads();
#pragma unroll
    for (int off = 1; off < 128; off <<= 1) {
        int u = (t >= off) ? s[t - off] : 0;
        __syncthreads();
        s[t] += u;
        __syncthreads();
    }
    if (t < SCAN_G) g_boff[t] = s[t] - v;  // exclusive
    if (t == 127)   g_ptr[N_NODES] = s[127];
}

// atomic-free scatter into CSR (boff folded inline)
__global__ void k_scatter(int E) {
    int e = blockIdx.x * blockDim.x + threadIdx.x;
    if (e >= E) return;
    unsigned long long p = g_pack[e];
    int s = (int)(p & 0xFFFFFu);
    int d = (int)((p >> 20) & 0xFFFFFu);
    int r = (int)(p >> 40);
    g_csr[g_ptr[d] + g_boff[d >> 10] + r] = s;
}

// -------- GEMM: h1 = x @ W1 (FFMA2 inner product) --------
#define KC 32
#define XS_STRIDE 36

__global__ void __launch_bounds__(256) k_gemm1(const float* __restrict__ x,
                                               const float* __restrict__ W1) {
    __shared__ float xs[256 * XS_STRIDE];
    __shared__ float wc[KC * 16];
    int t = threadIdx.x;
    int rbase = blockIdx.x * 256;

    unsigned long long acc[8];
#pragma unroll
    for (int j = 0; j < 8; j++) acc[j] = 0ull;

    for (int kb = 0; kb < F_IN; kb += KC) {
        __syncthreads();
#pragma unroll
        for (int i = 0; i < 8; i++) {
            int flat = t + 256 * i;
            int row  = flat >> 3;
            int k4   = flat & 7;
            float4 v = make_float4(0.f, 0.f, 0.f, 0.f);
            int gr = rbase + row;
            if (gr < N_NODES)
                v = *(const float4*)(x + (size_t)gr * F_IN + kb + k4 * 4);
            *(float4*)(xs + row * XS_STRIDE + k4 * 4) = v;
        }
        if (t < 128)
            *(float4*)(wc + t * 4) = *(const float4*)(W1 + kb * 16 + t * 4);
        __syncthreads();

#pragma unroll
        for (int k4 = 0; k4 < 8; k4++) {
            float4 xv = *(float4*)(xs + t * XS_STRIDE + k4 * 4);
            float xk[4] = {xv.x, xv.y, xv.z, xv.w};
#pragma unroll
            for (int c = 0; c < 4; c++) {
                int k = k4 * 4 + c;
                unsigned long long xx;
                asm("mov.b64 %0, {%1,%1};" : "=l"(xx) : "f"(xk[c]));
                const unsigned long long* wr =
                    (const unsigned long long*)(wc + k * 16);
#pragma unroll
                for (int j = 0; j < 8; j++)
                    asm("fma.rn.f32x2 %0, %1, %2, %0;"
                        : "+l"(acc[j]) : "l"(xx), "l"(wr[j]));
            }
        }
    }

    int r = rbase + t;
    if (r < N_NODES) {
        float4* hp = (float4*)(g_h1 + (size_t)r * 16);
#pragma unroll
        for (int q = 0; q < 4; q++) {
            float lo0, hi0, lo1, hi1;
            asm("mov.b64 {%0,%1}, %2;" : "=f"(lo0), "=f"(hi0) : "l"(acc[2 * q]));
            asm("mov.b64 {%0,%1}, %2;" : "=f"(lo1), "=f"(hi1) : "l"(acc[2 * q + 1]));
            hp[q] = make_float4(lo0, hi0, lo1, hi1);
        }
    }
}

// -------- layer 1 aggregate (CSR gather, 4-wide) fused with layer 2 transform --------
__global__ void __launch_bounds__(256) k_agg1x(const float* __restrict__ b1,
                                               const float* __restrict__ W2) {
    __shared__ float sW[128];
    int t = threadIdx.x;
    if (t < 112) sW[t] = W2[t];
    else if (t < 128) sW[t] = b1[t - 112];
    __syncthreads();

    int n = blockIdx.x * blockDim.x + t;
    if (n >= N_NODES) return;

    float di  = g_dinv[n];
    float di2 = di * di;
    float acc[16];
    {
        const float4* hp = (const float4*)(g_h1 + (size_t)n * 16);
#pragma unroll
        for (int q = 0; q < 4; q++) {
            float4 v = hp[q];
            acc[4 * q + 0] = v.x * di2;
            acc[4 * q + 1] = v.y * di2;
            acc[4 * q + 2] = v.z * di2;
            acc[4 * q + 3] = v.w * di2;
        }
    }
    int beg = ptr_at(n), end = ptr_at(n + 1);
    int i = beg;
    for (; i + 4 <= end; i += 4) {
        int   sj[4];
        float nj[4];
#pragma unroll
        for (int j = 0; j < 4; j++) sj[j] = __ldg(&g_csr[i + j]);
#pragma unroll
        for (int j = 0; j < 4; j++) nj[j] = __ldg(&g_dinv[sj[j]]) * di;
        float4 rows[4][4];
#pragma unroll
        for (int j = 0; j < 4; j++) {
            const float4* q0 = (const float4*)(g_h1 + (size_t)sj[j] * 16);
#pragma unroll
            for (int q = 0; q < 4; q++) rows[j][q] = __ldg(&q0[q]);
        }
#pragma unroll
        for (int j = 0; j < 4; j++)
#pragma unroll
            for (int q = 0; q < 4; q++) {
                acc[4 * q + 0] += rows[j][q].x * nj[j];
                acc[4 * q + 1] += rows[j][q].y * nj[j];
                acc[4 * q + 2] += rows[j][q].z * nj[j];
                acc[4 * q + 3] += rows[j][q].w * nj[j];
            }
    }
    for (; i < end; i++) {
        int s0 = __ldg(&g_csr[i]);
        float n0 = __ldg(&g_dinv[s0]) * di;
        const float4* q0 = (const float4*)(g_h1 + (size_t)s0 * 16);
#pragma unroll
        for (int q = 0; q < 4; q++) {
            float4 a = __ldg(&q0[q]);
            acc[4 * q + 0] += a.x * n0;
            acc[4 * q + 1] += a.y * n0;
            acc[4 * q + 2] += a.z * n0;
            acc[4 * q + 3] += a.w * n0;
        }
    }
    float v[16];
#pragma unroll
    for (int k = 0; k < 16; k++) v[k] = fmaxf(acc[k] + sW[112 + k], 0.f);
    float h[7];
#pragma unroll
    for (int j = 0; j < 7; j++) {
        float s = 0.f;
#pragma unroll
        for (int k = 0; k < 16; k++) s += v[k] * sW[k * 7 + j];
        h[j] = s;
    }
    float4* hp = (float4*)(g_h2 + (size_t)n * 8);
    hp[0] = make_float4(h[0], h[1], h[2], h[3]);
    hp[1] = make_float4(h[4], h[5], h[6], 0.f);
}

// -------- layer 2 aggregate (CSR gather, 4-wide), writes d_out --------
__global__ void __launch_bounds__(256) k_agg2(const float* __restrict__ b2,
                                              float* __restrict__ out) {
    int n = blockIdx.x * blockDim.x + threadIdx.x;
    if (n >= N_NODES) return;
    float di  = g_dinv[n];
    float di2 = di * di;
    float acc[7];
    {
        const float4* hp = (const float4*)(g_h2 + (size_t)n * 8);
        float4 a = hp[0], b = hp[1];
        acc[0] = a.x * di2 + __ldg(b2 + 0);
        acc[1] = a.y * di2 + __ldg(b2 + 1);
        acc[2] = a.z * di2 + __ldg(b2 + 2);
        acc[3] = a.w * di2 + __ldg(b2 + 3);
        acc[4] = b.x * di2 + __ldg(b2 + 4);
        acc[5] = b.y * di2 + __ldg(b2 + 5);
        acc[6] = b.z * di2 + __ldg(b2 + 6);
    }
    int beg = ptr_at(n), end = ptr_at(n + 1);
    int i = beg;
    for (; i + 4 <= end; i += 4) {
        int   sj[4];
        float nj[4];
#pragma unroll
        for (int j = 0; j < 4; j++) sj[j] = __ldg(&g_csr[i + j]);
#pragma unroll
        for (int j = 0; j < 4; j++) nj[j] = __ldg(&g_dinv[sj[j]]) * di;
        float4 r0[4], r1[4];
#pragma unroll
        for (int j = 0; j < 4; j++) {
            const float4* p0 = (const float4*)(g_h2 + (size_t)sj[j] * 8);
            r0[j] = __ldg(&p0[0]);
            r1[j] = __ldg(&p0[1]);
        }
#pragma unroll
        for (int j = 0; j < 4; j++) {
            acc[0] += r0[j].x * nj[j];
            acc[1] += r0[j].y * nj[j];
            acc[2] += r0[j].z * nj[j];
            acc[3] += r0[j].w * nj[j];
            acc[4] += r1[j].x * nj[j];
            acc[5] += r1[j].y * nj[j];
            acc[6] += r1[j].z * nj[j];
        }
    }
    for (; i < end; i++) {
        int s0 = __ldg(&g_csr[i]);
        float n0 = __ldg(&g_dinv[s0]) * di;
        const float4* p0 = (const float4*)(g_h2 + (size_t)s0 * 8);
        float4 a0 = __ldg(&p0[0]), a1 = __ldg(&p0[1]);
        acc[0] += a0.x * n0;
        acc[1] += a0.y * n0;
        acc[2] += a0.z * n0;
        acc[3] += a0.w * n0;
        acc[4] += a1.x * n0;
        acc[5] += a1.y * n0;
        acc[6] += a1.z * n0;
    }
    float* op = out + (size_t)n * 7;
#pragma unroll
    for (int j = 0; j < 7; j++) op[j] = acc[j];
}

extern "C" void kernel_launch(void* const* d_in, const int* in_sizes, int n_in,
                              void* d_out, int out_size) {
    const float* x  = (const float*)d_in[0];
    const void*  ei = d_in[1];
    const float* W1 = (const float*)d_in[2];
    const float* b1 = (const float*)d_in[3];
    const float* W2 = (const float*)d_in[4];
    const float* b2 = (const float*)d_in[5];
    int E = in_sizes[1] / 2;

    k_init<<<(N_NODES + 255) / 256, 256>>>((const unsigned int*)ei);  // 0
    k_convert<<<(E + 255) / 256, 256>>>(ei, E);                        // 1
    k_scan1<<<SCAN_G, SCAN_B>>>();                                     // 2
    k_gemm1<<<(N_NODES + 255) / 256, 256>>>(x, W1);                    // 3 <- profiled
    k_scan2<<<1, 128>>>();                                             // 4
    k_scatter<<<(E + 255) / 256, 256>>>(E);                            // 5
    k_agg1x<<<(N_NODES + 255) / 256, 256>>>(b1, W2);                   // 6
    k_agg2<<<(N_NODES + 255) / 256, 256>>>(b2, (float*)d_out);         // 7
}